// round 1
// baseline (speedup 1.0000x reference)
#include <cuda_runtime.h>
#include <cuda_fp16.h>

#define Bn 4
#define Cc 64
#define Hh 128
#define Wwidth 128
#define Gg 8
#define HW (128*128)

// -------- scratch (static device allocations; no cudaMalloc allowed) --------
__device__ float  g_om [Bn*216*HW];   // raw conv_om output (offsets 0..143, mask logits 144..215)
__device__ float  g_em1[Bn*64*HW];    // em after leaky
__device__ float  g_em [Bn*72*HW];    // sigmoid(conv em2)
__device__ __half g_xh [(size_t)Bn*64*HW]; // x  transposed to [B*G, H, W, 8] fp16
__device__ __half g_sh [(size_t)Bn*64*HW]; // share transposed

// ---------------------------------------------------------------------------
// Generic 3x3 conv, pad=1, stride=1. Register-tiled: 128 threads, each thread
// computes 4 pixels x 16 output channels. Input channels chunked by 8 through
// shared memory. Supports a 2-tensor channel concat via (in0,in1,c0).
// ACT: 0=none 1=leaky(0.1) 2=sigmoid
// ---------------------------------------------------------------------------
template<int CIN, int ACT>
__global__ void __launch_bounds__(128) conv3x3_kernel(
    const float* __restrict__ in0, const float* __restrict__ in1, int c0,
    const float* __restrict__ wgt, const float* __restrict__ bias,
    float* __restrict__ out, int COUT)
{
    __shared__ float s_in[8][18][34];
    __shared__ float s_w[16][8][9];

    const int tid   = threadIdx.x;
    const int tx    = tid & 31;
    const int ty    = tid >> 5;          // 0..3
    const int tileX = blockIdx.x & 3;    // W/32
    const int tileY = blockIdx.x >> 2;   // H/16
    const int b     = blockIdx.y;
    const int coBase = blockIdx.z * 16;
    const int gx0 = tileX * 32, gy0 = tileY * 16;

    float acc[4][16];
    #pragma unroll
    for (int p = 0; p < 4; p++)
        #pragma unroll
        for (int co = 0; co < 16; co++) acc[p][co] = 0.f;

    for (int cb = 0; cb < CIN / 8; cb++) {
        // ---- weights for this (co tile, cin chunk): 16*8*9 = 1152 = 9/thread
        #pragma unroll
        for (int e = tid; e < 16 * 72; e += 128) {
            int col = e / 72;
            int rem = e % 72;
            int c = rem / 9, t = rem % 9;
            int co = coBase + col;
            float v = 0.f;
            if (co < COUT) v = wgt[(co * CIN + cb * 8 + c) * 9 + t];
            s_w[col][c][t] = v;
        }
        // ---- input tile with halo: 8 ch x 18 x 34
        const bool first = (cb * 8 < c0);
        const float* src = first ? in0 : in1;
        const int chBase = first ? cb * 8 : cb * 8 - c0;
        const int nch    = first ? c0 : (CIN - c0);
        for (int e = tid; e < 8 * 18 * 34; e += 128) {
            int c   = e / (18 * 34);
            int rem = e % (18 * 34);
            int r   = rem / 34, col = rem % 34;
            int gy = gy0 + r - 1, gx = gx0 + col - 1;
            float v = 0.f;
            if (gy >= 0 && gy < Hh && gx >= 0 && gx < Wwidth)
                v = src[(size_t)(b * nch + chBase + c) * HW + gy * Wwidth + gx];
            s_in[c][r][col] = v;
        }
        __syncthreads();

        #pragma unroll
        for (int c = 0; c < 8; c++) {
            float xv[4][9];
            #pragma unroll
            for (int p = 0; p < 4; p++) {
                int R = ty + 4 * p;
                #pragma unroll
                for (int dr = 0; dr < 3; dr++)
                    #pragma unroll
                    for (int dc = 0; dc < 3; dc++)
                        xv[p][dr * 3 + dc] = s_in[c][R + dr][tx + dc];
            }
            #pragma unroll
            for (int t = 0; t < 9; t++) {
                #pragma unroll
                for (int co = 0; co < 16; co++) {
                    float wv = s_w[co][c][t];
                    #pragma unroll
                    for (int p = 0; p < 4; p++)
                        acc[p][co] = fmaf(xv[p][t], wv, acc[p][co]);
                }
            }
        }
        __syncthreads();
    }

    #pragma unroll
    for (int co = 0; co < 16; co++) {
        int oc = coBase + co;
        if (oc >= COUT) break;
        float bv = bias[oc];
        #pragma unroll
        for (int p = 0; p < 4; p++) {
            float v = acc[p][co] + bv;
            if (ACT == 1) v = (v >= 0.f) ? v : 0.1f * v;
            if (ACT == 2) v = 1.f / (1.f + __expf(-v));
            out[(size_t)(b * COUT + oc) * HW + (gy0 + ty + 4 * p) * Wwidth + (gx0 + tx)] = v;
        }
    }
}

// ---------------------------------------------------------------------------
// NCHW fp32 -> [B*G, H, W, 8ch] fp16 (one 16B store per thread)
// ---------------------------------------------------------------------------
__global__ void __launch_bounds__(128) transpose_kernel(
    const float* __restrict__ in, __half* __restrict__ out)
{
    const int w  = threadIdx.x;
    const int h  = blockIdx.x & 127;
    const int bg = blockIdx.x >> 7;        // b*8+g
    const int b  = bg >> 3, g = bg & 7;
    const float* src = in + (size_t)(b * 64 + g * 8) * HW + h * Wwidth + w;
    __half hv[8];
    #pragma unroll
    for (int c = 0; c < 8; c++) hv[c] = __float2half_rn(src[(size_t)c * HW]);
    *(uint4*)(out + ((size_t)bg * HW + h * Wwidth + w) * 8) = *(const uint4*)hv;
}

// ---------------------------------------------------------------------------
// bilinear gather of 8 contiguous fp16 channels at 4 corners, scaled by mask
// ---------------------------------------------------------------------------
__device__ __forceinline__ void bilin8(
    const __half* __restrict__ base,
    int i00, int i01, int i10, int i11,
    float w00, float w01, float w10, float w11,
    float scale, float* v)
{
    float4 r00 = *(const float4*)(base + i00);
    float4 r01 = *(const float4*)(base + i01);
    float4 r10 = *(const float4*)(base + i10);
    float4 r11 = *(const float4*)(base + i11);
    const __half2* h00 = (const __half2*)&r00;
    const __half2* h01 = (const __half2*)&r01;
    const __half2* h10 = (const __half2*)&r10;
    const __half2* h11 = (const __half2*)&r11;
    #pragma unroll
    for (int j = 0; j < 4; j++) {
        float2 f00 = __half22float2(h00[j]);
        float2 f01 = __half22float2(h01[j]);
        float2 f10 = __half22float2(h10[j]);
        float2 f11 = __half22float2(h11[j]);
        v[2 * j]     = (w00 * f00.x + w01 * f01.x + w10 * f10.x + w11 * f11.x) * scale;
        v[2 * j + 1] = (w00 * f00.y + w01 * f01.y + w10 * f10.y + w11 * f11.y) * scale;
    }
}

// ---------------------------------------------------------------------------
// Both deformable convs in one pass (shared offsets, shared w_dc).
// Block = one output row for one (b, g); thread = one pixel; 8 couts each.
// ---------------------------------------------------------------------------
__global__ void __launch_bounds__(128) deform_kernel(
    const float* __restrict__ w_dc, const float* __restrict__ b_dc,
    float* __restrict__ out)
{
    __shared__ float s_w[8][8][9];  // [co_local][c][kk]
    __shared__ float s_b[8];

    const int w  = threadIdx.x;
    const int h  = blockIdx.x;
    const int bg = blockIdx.y;
    const int b  = bg >> 3, g = bg & 7;

    for (int e = threadIdx.x; e < 576; e += 128) {
        int co = e / 72, rem = e % 72;
        s_w[co][rem / 9][rem % 9] = w_dc[(g * 8) * 72 + e];
    }
    if (threadIdx.x < 8) s_b[threadIdx.x] = b_dc[g * 8 + threadIdx.x];
    __syncthreads();

    const int pix = h * Wwidth + w;
    const float*  omB = g_om + (size_t)b * 216 * HW + pix;
    const float*  emB = g_em + (size_t)b * 72 * HW + pix;
    const __half* xg  = g_xh + (size_t)bg * HW * 8;
    const __half* sg  = g_sh + (size_t)bg * HW * 8;

    float ax[8], as2[8];
    #pragma unroll
    for (int i = 0; i < 8; i++) { ax[i] = 0.f; as2[i] = 0.f; }

    #pragma unroll
    for (int kk = 0; kk < 9; kk++) {
        const int kh = kk / 3, kw = kk % 3;
        float dy = omB[(size_t)(g * 18 + 2 * kk) * HW];
        float dx = omB[(size_t)(g * 18 + 2 * kk + 1) * HW];
        float mz = omB[(size_t)(144 + g * 9 + kk) * HW];
        float mx = 1.f / (1.f + __expf(-mz));
        float me = emB[(size_t)(g * 9 + kk) * HW];

        float py = (float)(h - 1 + kh) + dy;
        float px = (float)(w - 1 + kw) + dx;
        float fy = floorf(py), fx = floorf(px);
        float ly = py - fy, lx = px - fx;
        int y0 = (int)fy, x0 = (int)fx;
        int y1 = y0 + 1, x1 = x0 + 1;

        float w00 = (1.f - ly) * (1.f - lx);
        float w01 = (1.f - ly) * lx;
        float w10 = ly * (1.f - lx);
        float w11 = ly * lx;
        if (y0 < 0 || y0 >= Hh)     { w00 = 0.f; w01 = 0.f; }
        if (y1 < 0 || y1 >= Hh)     { w10 = 0.f; w11 = 0.f; }
        if (x0 < 0 || x0 >= Wwidth) { w00 = 0.f; w10 = 0.f; }
        if (x1 < 0 || x1 >= Wwidth) { w01 = 0.f; w11 = 0.f; }

        int cy0 = min(max(y0, 0), Hh - 1),     cy1 = min(max(y1, 0), Hh - 1);
        int cx0 = min(max(x0, 0), Wwidth - 1), cx1 = min(max(x1, 0), Wwidth - 1);
        int i00 = (cy0 * Wwidth + cx0) * 8, i01 = (cy0 * Wwidth + cx1) * 8;
        int i10 = (cy1 * Wwidth + cx0) * 8, i11 = (cy1 * Wwidth + cx1) * 8;

        float vx[8], vs[8];
        bilin8(xg, i00, i01, i10, i11, w00, w01, w10, w11, mx, vx);
        bilin8(sg, i00, i01, i10, i11, w00, w01, w10, w11, me, vs);

        #pragma unroll
        for (int c = 0; c < 8; c++) {
            #pragma unroll
            for (int co = 0; co < 8; co++) {
                float wv = s_w[co][c][kk];
                ax[co]  = fmaf(wv, vx[c], ax[co]);
                as2[co] = fmaf(wv, vs[c], as2[co]);
            }
        }
    }

    float* outx = out + (size_t)(b * 64 + g * 8) * HW + pix;
    float* outs = outx + (size_t)Bn * 64 * HW;
    #pragma unroll
    for (int co = 0; co < 8; co++) {
        outx[(size_t)co * HW] = ax[co] + s_b[co];
        outs[(size_t)co * HW] = as2[co] + s_b[co];
    }
}

// ---------------------------------------------------------------------------
extern "C" void kernel_launch(void* const* d_in, const int* in_sizes, int n_in,
                              void* d_out, int out_size)
{
    const float* x      = (const float*)d_in[0];
    const float* share  = (const float*)d_in[1];
    const float* offF   = (const float*)d_in[2];
    const float* w_om   = (const float*)d_in[3];
    const float* b_om   = (const float*)d_in[4];
    const float* w_em1  = (const float*)d_in[5];
    const float* b_em1  = (const float*)d_in[6];
    const float* w_em2  = (const float*)d_in[7];
    const float* b_em2  = (const float*)d_in[8];
    const float* w_dc   = (const float*)d_in[9];
    const float* b_dc   = (const float*)d_in[10];
    float* out = (float*)d_out;

    float *pom, *pem1, *pem;
    __half *pxh, *psh;
    cudaGetSymbolAddress((void**)&pom,  g_om);
    cudaGetSymbolAddress((void**)&pem1, g_em1);
    cudaGetSymbolAddress((void**)&pem,  g_em);
    cudaGetSymbolAddress((void**)&pxh,  g_xh);
    cudaGetSymbolAddress((void**)&psh,  g_sh);

    dim3 blk(128);
    // om = conv3x3(offset_feat) -> 216 ch (raw; sigmoid on mask applied in deform)
    conv3x3_kernel<64, 0><<<dim3(32, 4, 14), blk>>>(offF, offF, 64, w_om, b_om, pom, 216);
    // em1 = leaky(conv3x3(cat[share, offset_feat]))
    conv3x3_kernel<128, 1><<<dim3(32, 4, 4), blk>>>(share, offF, 64, w_em1, b_em1, pem1, 64);
    // em = sigmoid(conv3x3(em1)) -> 72 ch
    conv3x3_kernel<64, 2><<<dim3(32, 4, 5), blk>>>(pem1, pem1, 64, w_em2, b_em2, pem, 72);
    // transpose sampled tensors to [B*G, H, W, 8] fp16
    transpose_kernel<<<4096, 128>>>(x, pxh);
    transpose_kernel<<<4096, 128>>>(share, psh);
    // both deformable convolutions in one kernel
    deform_kernel<<<dim3(128, 32), 128>>>(w_dc, b_dc, out);

    (void)in_sizes; (void)n_in; (void)out_size;
}

// round 2
// speedup vs baseline: 1.3457x; 1.3457x over previous
#include <cuda_runtime.h>
#include <cuda_fp16.h>

#define Bn 4
#define Cc 64
#define Hh 128
#define Wwidth 128
#define Gg 8
#define HW (128*128)

typedef unsigned long long ull;

// ---------------- packed fp32x2 helpers (sm_103a FFMA2 via explicit PTX) ----
__device__ __forceinline__ ull pk(float lo, float hi) {
    ull r; asm("mov.b64 %0, {%1,%2};" : "=l"(r) : "f"(lo), "f"(hi)); return r;
}
__device__ __forceinline__ void upk(ull v, float& lo, float& hi) {
    asm("mov.b64 {%0,%1}, %2;" : "=f"(lo), "=f"(hi) : "l"(v));
}
__device__ __forceinline__ ull ffma2(ull a, ull b, ull c) {
    ull d; asm("fma.rn.f32x2 %0, %1, %2, %3;" : "=l"(d) : "l"(a), "l"(b), "l"(c)); return d;
}

// -------- scratch (static device allocations; no cudaMalloc allowed) --------
__device__ float  g_om [Bn*216*HW];   // raw conv_om output (offsets 0..143, mask logits 144..215)
__device__ float  g_em1[Bn*64*HW];    // em after leaky
__device__ float  g_em [Bn*72*HW];    // sigmoid(conv em2)
__device__ __half g_xh [(size_t)Bn*64*HW]; // x  transposed to [B*G, H, W, 8] fp16
__device__ __half g_sh [(size_t)Bn*64*HW]; // share transposed

// ---------------------------------------------------------------------------
// Generic 3x3 conv, pad=1, stride=1. Register-tiled: 128 threads, each thread
// computes 4 pixels x 16 output channels, accumulated as 8 f32x2 co-pairs via
// packed FFMA2. Input channels chunked by 8 through shared memory.
// ACT: 0=none 1=leaky(0.1) 2=sigmoid
// ---------------------------------------------------------------------------
template<int CIN, int ACT>
__global__ void __launch_bounds__(128) conv3x3_kernel(
    const float* __restrict__ in0, const float* __restrict__ in1, int c0,
    const float* __restrict__ wgt, const float* __restrict__ bias,
    float* __restrict__ out, int COUT)
{
    __shared__ float s_in[8][18][34];
    __shared__ __align__(16) float s_w[8][9][16];   // [cin][tap][co] — co contiguous

    const int tid   = threadIdx.x;
    const int tx    = tid & 31;
    const int ty    = tid >> 5;          // 0..3
    const int tileX = blockIdx.x & 3;    // W/32
    const int tileY = blockIdx.x >> 2;   // H/16
    const int b     = blockIdx.y;
    const int coBase = blockIdx.z * 16;
    const int gx0 = tileX * 32, gy0 = tileY * 16;

    ull acc[4][8];
    #pragma unroll
    for (int p = 0; p < 4; p++)
        #pragma unroll
        for (int j = 0; j < 8; j++) acc[p][j] = 0ull;

    for (int cb = 0; cb < CIN / 8; cb++) {
        // ---- weights for this (co tile, cin chunk): layout [c][t][co]
        #pragma unroll
        for (int e = tid; e < 8 * 9 * 16; e += 128) {
            int c = e / 144;
            int r = e % 144;
            int t = r / 16, co = r % 16;
            int oc = coBase + co;
            float v = 0.f;
            if (oc < COUT) v = wgt[((size_t)oc * CIN + cb * 8 + c) * 9 + t];
            s_w[c][t][co] = v;
        }
        // ---- input tile with halo: 8 ch x 18 x 34
        const bool first = (cb * 8 < c0);
        const float* src = first ? in0 : in1;
        const int chBase = first ? cb * 8 : cb * 8 - c0;
        const int nch    = first ? c0 : (CIN - c0);
        for (int e = tid; e < 8 * 18 * 34; e += 128) {
            int c   = e / (18 * 34);
            int rem = e % (18 * 34);
            int r   = rem / 34, col = rem % 34;
            int gy = gy0 + r - 1, gx = gx0 + col - 1;
            float v = 0.f;
            if (gy >= 0 && gy < Hh && gx >= 0 && gx < Wwidth)
                v = src[(size_t)(b * nch + chBase + c) * HW + gy * Wwidth + gx];
            s_in[c][r][col] = v;
        }
        __syncthreads();

        #pragma unroll
        for (int c = 0; c < 8; c++) {
            #pragma unroll
            for (int t = 0; t < 9; t++) {
                const int dr = t / 3, dc = t % 3;
                ull wp[8];
                #pragma unroll
                for (int j = 0; j < 8; j++)
                    wp[j] = *(const ull*)&s_w[c][t][2 * j];
                #pragma unroll
                for (int p = 0; p < 4; p++) {
                    float v = s_in[c][ty + 4 * p + dr][tx + dc];
                    ull vs = pk(v, v);
                    #pragma unroll
                    for (int j = 0; j < 8; j++)
                        acc[p][j] = ffma2(vs, wp[j], acc[p][j]);
                }
            }
        }
        __syncthreads();
    }

    #pragma unroll
    for (int j = 0; j < 8; j++) {
        int oc0 = coBase + 2 * j;
        int oc1 = oc0 + 1;
        float b0 = (oc0 < COUT) ? bias[oc0] : 0.f;
        float b1 = (oc1 < COUT) ? bias[oc1] : 0.f;
        #pragma unroll
        for (int p = 0; p < 4; p++) {
            float v0, v1;
            upk(acc[p][j], v0, v1);
            v0 += b0; v1 += b1;
            if (ACT == 1) { v0 = (v0 >= 0.f) ? v0 : 0.1f * v0; v1 = (v1 >= 0.f) ? v1 : 0.1f * v1; }
            if (ACT == 2) { v0 = 1.f / (1.f + __expf(-v0)); v1 = 1.f / (1.f + __expf(-v1)); }
            size_t pix = (size_t)(gy0 + ty + 4 * p) * Wwidth + (gx0 + tx);
            if (oc0 < COUT) out[(size_t)(b * COUT + oc0) * HW + pix] = v0;
            if (oc1 < COUT) out[(size_t)(b * COUT + oc1) * HW + pix] = v1;
        }
    }
}

// ---------------------------------------------------------------------------
// NCHW fp32 -> [B*G, H, W, 8ch] fp16 (one 16B store per thread)
// ---------------------------------------------------------------------------
__global__ void __launch_bounds__(128) transpose_kernel(
    const float* __restrict__ in, __half* __restrict__ out)
{
    const int w  = threadIdx.x;
    const int h  = blockIdx.x & 127;
    const int bg = blockIdx.x >> 7;        // b*8+g
    const int b  = bg >> 3, g = bg & 7;
    const float* src = in + (size_t)(b * 64 + g * 8) * HW + h * Wwidth + w;
    __half hv[8];
    #pragma unroll
    for (int c = 0; c < 8; c++) hv[c] = __float2half_rn(src[(size_t)c * HW]);
    *(uint4*)(out + ((size_t)bg * HW + h * Wwidth + w) * 8) = *(const uint4*)hv;
}

// ---------------------------------------------------------------------------
// Both deformable convs: 256-thread blocks; warps 0-3 compute x_deform,
// warps 4-7 compute share_deform for the same 128-pixel row. Shared smem
// weights; offset (om) lines shared through L1. FFMA2 co-pair accumulation.
// ---------------------------------------------------------------------------
__global__ void __launch_bounds__(256) deform_kernel(
    const float* __restrict__ w_dc, const float* __restrict__ b_dc,
    float* __restrict__ out)
{
    __shared__ __align__(16) float s_w[8][9][8];  // [c][kk][co] — co contiguous
    __shared__ float s_b[8];

    const int tid  = threadIdx.x;
    const int half = tid >> 7;            // 0 = x path, 1 = share path
    const int w    = tid & 127;
    const int h    = blockIdx.x;
    const int bg   = blockIdx.y;
    const int b    = bg >> 3, g = bg & 7;

    for (int e = tid; e < 576; e += 256) {
        int c = e / 72, r = e % 72;
        int kk = r / 8, co = r % 8;
        s_w[c][kk][co] = w_dc[((size_t)(g * 8 + co) * 8 + c) * 9 + kk];
    }
    if (tid < 8) s_b[tid] = b_dc[g * 8 + tid];
    __syncthreads();

    const int pix = h * Wwidth + w;
    const float*  omB = g_om + (size_t)b * 216 * HW + pix;
    const float*  emB = g_em + (size_t)b * 72 * HW + pix;
    const __half* src = (half ? g_sh : g_xh) + (size_t)bg * HW * 8;

    ull acc[4];
    #pragma unroll
    for (int j = 0; j < 4; j++) acc[j] = 0ull;

    #pragma unroll
    for (int kk = 0; kk < 9; kk++) {
        const int kh = kk / 3, kw = kk % 3;
        float dy = omB[(size_t)(g * 18 + 2 * kk) * HW];
        float dx = omB[(size_t)(g * 18 + 2 * kk + 1) * HW];
        float mask;
        if (half == 0) {
            float mz = omB[(size_t)(144 + g * 9 + kk) * HW];
            mask = 1.f / (1.f + __expf(-mz));
        } else {
            mask = emB[(size_t)(g * 9 + kk) * HW];
        }

        float py = (float)(h - 1 + kh) + dy;
        float px = (float)(w - 1 + kw) + dx;
        float fy = floorf(py), fx = floorf(px);
        float ly = py - fy, lx = px - fx;
        int y0 = (int)fy, x0 = (int)fx;
        int y1 = y0 + 1, x1 = x0 + 1;

        float w00 = (1.f - ly) * (1.f - lx);
        float w01 = (1.f - ly) * lx;
        float w10 = ly * (1.f - lx);
        float w11 = ly * lx;
        if (y0 < 0 || y0 >= Hh)     { w00 = 0.f; w01 = 0.f; }
        if (y1 < 0 || y1 >= Hh)     { w10 = 0.f; w11 = 0.f; }
        if (x0 < 0 || x0 >= Wwidth) { w00 = 0.f; w10 = 0.f; }
        if (x1 < 0 || x1 >= Wwidth) { w01 = 0.f; w11 = 0.f; }

        int cy0 = min(max(y0, 0), Hh - 1),     cy1 = min(max(y1, 0), Hh - 1);
        int cx0 = min(max(x0, 0), Wwidth - 1), cx1 = min(max(x1, 0), Wwidth - 1);
        int i00 = (cy0 * Wwidth + cx0) * 8, i01 = (cy0 * Wwidth + cx1) * 8;
        int i10 = (cy1 * Wwidth + cx0) * 8, i11 = (cy1 * Wwidth + cx1) * 8;

        float4 r00 = *(const float4*)(src + i00);
        float4 r01 = *(const float4*)(src + i01);
        float4 r10 = *(const float4*)(src + i10);
        float4 r11 = *(const float4*)(src + i11);
        const __half2* h00 = (const __half2*)&r00;
        const __half2* h01 = (const __half2*)&r01;
        const __half2* h10 = (const __half2*)&r10;
        const __half2* h11 = (const __half2*)&r11;

        float vv[8];
        #pragma unroll
        for (int j2 = 0; j2 < 4; j2++) {
            float2 f00 = __half22float2(h00[j2]);
            float2 f01 = __half22float2(h01[j2]);
            float2 f10 = __half22float2(h10[j2]);
            float2 f11 = __half22float2(h11[j2]);
            vv[2 * j2]     = (w00 * f00.x + w01 * f01.x + w10 * f10.x + w11 * f11.x) * mask;
            vv[2 * j2 + 1] = (w00 * f00.y + w01 * f01.y + w10 * f10.y + w11 * f11.y) * mask;
        }

        #pragma unroll
        for (int c = 0; c < 8; c++) {
            ull xs = pk(vv[c], vv[c]);
            #pragma unroll
            for (int j = 0; j < 4; j++) {
                ull wp = *(const ull*)&s_w[c][kk][2 * j];
                acc[j] = ffma2(xs, wp, acc[j]);
            }
        }
    }

    float* ob = out + (size_t)half * Bn * 64 * HW + (size_t)(b * 64 + g * 8) * HW + pix;
    #pragma unroll
    for (int j = 0; j < 4; j++) {
        float v0, v1;
        upk(acc[j], v0, v1);
        ob[(size_t)(2 * j) * HW]     = v0 + s_b[2 * j];
        ob[(size_t)(2 * j + 1) * HW] = v1 + s_b[2 * j + 1];
    }
}

// ---------------------------------------------------------------------------
extern "C" void kernel_launch(void* const* d_in, const int* in_sizes, int n_in,
                              void* d_out, int out_size)
{
    const float* x      = (const float*)d_in[0];
    const float* share  = (const float*)d_in[1];
    const float* offF   = (const float*)d_in[2];
    const float* w_om   = (const float*)d_in[3];
    const float* b_om   = (const float*)d_in[4];
    const float* w_em1  = (const float*)d_in[5];
    const float* b_em1  = (const float*)d_in[6];
    const float* w_em2  = (const float*)d_in[7];
    const float* b_em2  = (const float*)d_in[8];
    const float* w_dc   = (const float*)d_in[9];
    const float* b_dc   = (const float*)d_in[10];
    float* out = (float*)d_out;

    float *pom, *pem1, *pem;
    __half *pxh, *psh;
    cudaGetSymbolAddress((void**)&pom,  g_om);
    cudaGetSymbolAddress((void**)&pem1, g_em1);
    cudaGetSymbolAddress((void**)&pem,  g_em);
    cudaGetSymbolAddress((void**)&pxh,  g_xh);
    cudaGetSymbolAddress((void**)&psh,  g_sh);

    dim3 blk(128);
    // om = conv3x3(offset_feat) -> 216 ch (raw; sigmoid on mask applied in deform)
    conv3x3_kernel<64, 0><<<dim3(32, 4, 14), blk>>>(offF, offF, 64, w_om, b_om, pom, 216);
    // em1 = leaky(conv3x3(cat[share, offset_feat]))
    conv3x3_kernel<128, 1><<<dim3(32, 4, 4), blk>>>(share, offF, 64, w_em1, b_em1, pem1, 64);
    // em = sigmoid(conv3x3(em1)) -> 72 ch
    conv3x3_kernel<64, 2><<<dim3(32, 4, 5), blk>>>(pem1, pem1, 64, w_em2, b_em2, pem, 72);
    // transpose sampled tensors to [B*G, H, W, 8] fp16
    transpose_kernel<<<4096, 128>>>(x, pxh);
    transpose_kernel<<<4096, 128>>>(share, psh);
    // both deformable convolutions in one kernel (x + share halves)
    deform_kernel<<<dim3(128, 32), 256>>>(w_dc, b_dc, out);

    (void)in_sizes; (void)n_in; (void)out_size;
}

// round 3
// speedup vs baseline: 2.2381x; 1.6632x over previous
#include <cuda_runtime.h>
#include <cuda_fp16.h>
#include <cuda_bf16.h>
#include <mma.h>

using namespace nvcuda;
typedef unsigned long long ull;
typedef __nv_bfloat16 bf16;

#define Bn 4
#define Hh 128
#define Wwidth 128
#define HW (128*128)

// ---------------- packed fp32x2 helpers (deform kernel) ---------------------
__device__ __forceinline__ ull pk(float lo, float hi) {
    ull r; asm("mov.b64 %0, {%1,%2};" : "=l"(r) : "f"(lo), "f"(hi)); return r;
}
__device__ __forceinline__ void upk(ull v, float& lo, float& hi) {
    asm("mov.b64 {%0,%1}, %2;" : "=f"(lo), "=f"(hi) : "l"(v));
}
__device__ __forceinline__ ull ffma2(ull a, ull b, ull c) {
    ull d; asm("fma.rn.f32x2 %0, %1, %2, %3;" : "=l"(d) : "l"(a), "l"(b), "l"(c)); return d;
}

// -------- scratch --------
__device__ float  g_om [Bn*216*HW];            // conv_om raw (fp32 NCHW)
__device__ float  g_em [Bn*72*HW];             // sigmoid(conv em2) fp32 NCHW
__device__ __half g_xh [(size_t)Bn*64*HW];     // x  as [B*G,H,W,8] fp16 (deform)
__device__ __half g_sh [(size_t)Bn*64*HW];     // share same
// channel-interleaved bf16 hi/lo planes: [b][chunk][h][w][ci16]
__device__ bf16 g_ofh[(size_t)Bn*64*HW], g_ofl[(size_t)Bn*64*HW];   // offset_feat
__device__ bf16 g_tsh[(size_t)Bn*64*HW], g_tsl[(size_t)Bn*64*HW];   // share
__device__ bf16 g_e1h[(size_t)Bn*64*HW], g_e1l[(size_t)Bn*64*HW];   // em1 output
// packed weights [CoP][Ktot], K = (chunk*9+tap)*16+ci
__device__ bf16 g_womh[256*576], g_woml[256*576];
__device__ bf16 g_we1h[64*1152], g_we1l[64*1152];
__device__ bf16 g_we2h[128*576], g_we2l[128*576];

// ---------------------------------------------------------------------------
// weight pack: w[Co][CIN][9] fp32 -> hi/lo bf16 [CoP][CIN*9] with K reorder
// ---------------------------------------------------------------------------
__global__ void pack_w_kernel(const float* __restrict__ w, bf16* __restrict__ dh,
                              bf16* __restrict__ dl, int Co, int CoP, int CIN)
{
    int idx = blockIdx.x * 256 + threadIdx.x;
    int Ktot = CIN * 9;
    if (idx >= CoP * Ktot) return;
    int co = idx / Ktot, k = idx % Ktot;
    int chunk = k / 144, rem = k % 144, tap = rem / 16, ci = rem % 16;
    int cin = chunk * 16 + ci;
    float v = (co < Co) ? w[((size_t)co * CIN + cin) * 9 + tap] : 0.f;
    bf16 h = __float2bfloat16(v);
    dh[idx] = h;
    dl[idx] = __float2bfloat16(v - __bfloat162float(h));
}

// ---------------------------------------------------------------------------
// input split+transpose: NCHW fp32 -> [b][chunk][h][w][ci16] bf16 hi/lo
// ---------------------------------------------------------------------------
__global__ void __launch_bounds__(128) split_t_kernel(
    const float* __restrict__ in, bf16* __restrict__ oh, bf16* __restrict__ ol)
{
    const int px = threadIdx.x;
    const int h = blockIdx.x, chunk = blockIdx.y, b = blockIdx.z;
    const float* src = in + (size_t)(b * 64 + chunk * 16) * HW + h * Wwidth + px;
    bf16 hv[16], lv[16];
    #pragma unroll
    for (int ci = 0; ci < 16; ci++) {
        float v = src[(size_t)ci * HW];
        bf16 hh = __float2bfloat16(v);
        hv[ci] = hh;
        lv[ci] = __float2bfloat16(v - __bfloat162float(hh));
    }
    size_t o = (((size_t)(b * 4 + chunk) * Hh + h) * Wwidth + px) * 16;
    ((uint4*)(oh + o))[0] = ((const uint4*)hv)[0];
    ((uint4*)(oh + o))[1] = ((const uint4*)hv)[1];
    ((uint4*)(ol + o))[0] = ((const uint4*)lv)[0];
    ((uint4*)(ol + o))[1] = ((const uint4*)lv)[1];
}

// ---------------------------------------------------------------------------
// Tensor-core implicit-GEMM 3x3 conv, pad=1. Block = one output row (128 px)
// x 64 co. 8 warps = 2 (coSub) x 4 (nSub). bf16 hi/lo 3-pass split (fp32-exact
// to ~1e-5). B fragments from channel-interleaved smem ([3][132][16]) so all
// shifted windows are 32B-aligned. ACT: 0 -> fp32 NCHW, 1 -> leaky + bf16
// hi/lo interleaved out, 2 -> sigmoid fp32 NCHW.
// ---------------------------------------------------------------------------
#define XSZ (3*132*16)      // elements per plane (input tile)
#define WSZ (64*144)        // elements per plane (weights)
#define SMEM_CONV ((2*XSZ + 2*WSZ) * 2)  // bytes = 62208

template<int CHUNKS, int C0CHUNKS, int ACT>
__global__ void __launch_bounds__(256) conv_wmma_kernel(
    const bf16* __restrict__ x0h, const bf16* __restrict__ x0l,
    const bf16* __restrict__ x1h, const bf16* __restrict__ x1l,
    const bf16* __restrict__ wAh, const bf16* __restrict__ wAl,
    const float* __restrict__ bias,
    float* __restrict__ outF, bf16* __restrict__ outH, bf16* __restrict__ outL,
    int Co)
{
    extern __shared__ __align__(16) char smem_raw[];
    bf16*  s_x = (bf16*)smem_raw;                       // [2][3][132][16]
    bf16*  s_w = (bf16*)(smem_raw + 2 * XSZ * 2);       // [2][64][144]
    float* sEp = (float*)smem_raw;                      // [64][136] (aliased)

    const int tid = threadIdx.x;
    const int h = blockIdx.x, b = blockIdx.y, coTile = blockIdx.z;
    const int warp = tid >> 5;
    const int coSub = warp >> 2;       // 0..1 (32 co each)
    const int nSub  = warp & 3;        // 0..3 (32 px each)
    const int Ktot  = CHUNKS * 144;

    wmma::fragment<wmma::accumulator, 16, 16, 16, float> acc[2][2];
    #pragma unroll
    for (int cf = 0; cf < 2; cf++)
        #pragma unroll
        for (int nf = 0; nf < 2; nf++) wmma::fill_fragment(acc[cf][nf], 0.f);

    // zero halo columns (scol 0, 129..131) once
    if (tid < 48) {
        int p = tid / 24, rem = tid % 24, r = rem / 8, q = rem % 8;
        int scol = (q >> 1) == 0 ? 0 : 128 + (q >> 1);
        uint4 z = {0, 0, 0, 0};
        ((uint4*)(s_x + (size_t)p * XSZ + (r * 132 + scol) * 16))[q & 1] = z;
    }

    for (int chunk = 0; chunk < CHUNKS; chunk++) {
        // ---- input tile fill (vector copy from interleaved GMEM)
        const bf16 *baseH, *baseL;
        if (chunk < C0CHUNKS) {
            size_t o = ((size_t)b * C0CHUNKS + chunk) * HW * 16;
            baseH = x0h + o; baseL = x0l + o;
        } else {
            size_t o = ((size_t)b * (CHUNKS - C0CHUNKS) + (chunk - C0CHUNKS)) * HW * 16;
            baseH = x1h + o; baseL = x1l + o;
        }
        for (int u = tid; u < 1536; u += 256) {
            int plane = u / 768, rem = u - plane * 768;
            int r = rem >> 8, c = rem & 255;
            int row = h - 1 + r;
            uint4 v = {0, 0, 0, 0};
            if (row >= 0 && row < Hh)
                v = *(const uint4*)((plane ? baseL : baseH) + (size_t)row * 2048 + c * 8);
            *(uint4*)(s_x + (size_t)plane * XSZ + (r * 132 + 1) * 16 + c * 8) = v;
        }
        // ---- weights fill
        for (int u = tid; u < 2304; u += 256) {
            int plane = u / 1152, rem = u - plane * 1152;
            int co = rem / 18, c = rem - co * 18;
            const bf16* s = (plane ? wAl : wAh)
                            + (size_t)(coTile * 64 + co) * Ktot + chunk * 144 + c * 8;
            *(uint4*)(s_w + (size_t)plane * WSZ + co * 144 + c * 8) = *(const uint4*)s;
        }
        __syncthreads();

        #pragma unroll
        for (int tap = 0; tap < 9; tap++) {
            const int dr = tap / 3, dc = tap % 3;
            wmma::fragment<wmma::matrix_a, 16, 16, 16, bf16, wmma::row_major> ah[2], al[2];
            #pragma unroll
            for (int cf = 0; cf < 2; cf++) {
                const bf16* p = s_w + (coSub * 32 + cf * 16) * 144 + tap * 16;
                wmma::load_matrix_sync(ah[cf], p, 144);
                wmma::load_matrix_sync(al[cf], p + WSZ, 144);
            }
            wmma::fragment<wmma::matrix_b, 16, 16, 16, bf16, wmma::col_major> bh[2], bl[2];
            #pragma unroll
            for (int nf = 0; nf < 2; nf++) {
                int scol = nSub * 32 + nf * 16 + dc;
                const bf16* p = s_x + (dr * 132 + scol) * 16;
                wmma::load_matrix_sync(bh[nf], p, 16);
                wmma::load_matrix_sync(bl[nf], p + XSZ, 16);
            }
            #pragma unroll
            for (int cf = 0; cf < 2; cf++)
                #pragma unroll
                for (int nf = 0; nf < 2; nf++) {
                    wmma::mma_sync(acc[cf][nf], ah[cf], bh[nf], acc[cf][nf]);
                    wmma::mma_sync(acc[cf][nf], ah[cf], bl[nf], acc[cf][nf]);
                    wmma::mma_sync(acc[cf][nf], al[cf], bh[nf], acc[cf][nf]);
                }
        }
        __syncthreads();
    }

    // ---- epilogue: frags -> smem -> GMEM
    #pragma unroll
    for (int cf = 0; cf < 2; cf++)
        #pragma unroll
        for (int nf = 0; nf < 2; nf++)
            wmma::store_matrix_sync(sEp + (coSub * 32 + cf * 16) * 136 + (nSub * 32 + nf * 16),
                                    acc[cf][nf], 136, wmma::mem_row_major);
    __syncthreads();

    const int px = tid & 127;
    if (ACT == 1) {
        const int hs = tid >> 7;
        #pragma unroll
        for (int q = 0; q < 2; q++) {
            int ch = hs * 2 + q;
            bf16 hv[16], lv[16];
            #pragma unroll
            for (int ci = 0; ci < 16; ci++) {
                int co = ch * 16 + ci;
                float v = sEp[co * 136 + px] + bias[co];
                v = (v >= 0.f) ? v : 0.1f * v;
                bf16 hh = __float2bfloat16(v);
                hv[ci] = hh;
                lv[ci] = __float2bfloat16(v - __bfloat162float(hh));
            }
            size_t o = (((size_t)(b * 4 + ch) * Hh + h) * Wwidth + px) * 16;
            ((uint4*)(outH + o))[0] = ((const uint4*)hv)[0];
            ((uint4*)(outH + o))[1] = ((const uint4*)hv)[1];
            ((uint4*)(outL + o))[0] = ((const uint4*)lv)[0];
            ((uint4*)(outL + o))[1] = ((const uint4*)lv)[1];
        }
    } else {
        for (int co = tid >> 7; co < 64; co += 2) {
            int oc = coTile * 64 + co;
            if (oc < Co) {
                float v = sEp[co * 136 + px] + bias[oc];
                if (ACT == 2) v = 1.f / (1.f + __expf(-v));
                outF[((size_t)b * Co + oc) * HW + h * Wwidth + px] = v;
            }
        }
    }
}

// ---------------------------------------------------------------------------
// NCHW fp32 -> [B*G, H, W, 8ch] fp16 (deform sampling layout)
// ---------------------------------------------------------------------------
__global__ void __launch_bounds__(128) transpose_kernel(
    const float* __restrict__ in, __half* __restrict__ out)
{
    const int w  = threadIdx.x;
    const int h  = blockIdx.x & 127;
    const int bg = blockIdx.x >> 7;
    const int b  = bg >> 3, g = bg & 7;
    const float* src = in + (size_t)(b * 64 + g * 8) * HW + h * Wwidth + w;
    __half hv[8];
    #pragma unroll
    for (int c = 0; c < 8; c++) hv[c] = __float2half_rn(src[(size_t)c * HW]);
    *(uint4*)(out + ((size_t)bg * HW + h * Wwidth + w) * 8) = *(const uint4*)hv;
}

// ---------------------------------------------------------------------------
// Both deformable convs: warps 0-3 -> x_deform, warps 4-7 -> share_deform.
// ---------------------------------------------------------------------------
__global__ void __launch_bounds__(256) deform_kernel(
    const float* __restrict__ w_dc, const float* __restrict__ b_dc,
    float* __restrict__ out)
{
    __shared__ __align__(16) float s_w[8][9][8];
    __shared__ float s_b[8];

    const int tid  = threadIdx.x;
    const int half = tid >> 7;
    const int w    = tid & 127;
    const int h    = blockIdx.x;
    const int bg   = blockIdx.y;
    const int b    = bg >> 3, g = bg & 7;

    for (int e = tid; e < 576; e += 256) {
        int c = e / 72, r = e % 72;
        int kk = r / 8, co = r % 8;
        s_w[c][kk][co] = w_dc[((size_t)(g * 8 + co) * 8 + c) * 9 + kk];
    }
    if (tid < 8) s_b[tid] = b_dc[g * 8 + tid];
    __syncthreads();

    const int pix = h * Wwidth + w;
    const float*  omB = g_om + (size_t)b * 216 * HW + pix;
    const float*  emB = g_em + (size_t)b * 72 * HW + pix;
    const __half* src = (half ? g_sh : g_xh) + (size_t)bg * HW * 8;

    ull acc[4];
    #pragma unroll
    for (int j = 0; j < 4; j++) acc[j] = 0ull;

    #pragma unroll
    for (int kk = 0; kk < 9; kk++) {
        const int kh = kk / 3, kw = kk % 3;
        float dy = omB[(size_t)(g * 18 + 2 * kk) * HW];
        float dx = omB[(size_t)(g * 18 + 2 * kk + 1) * HW];
        float mask;
        if (half == 0) {
            float mz = omB[(size_t)(144 + g * 9 + kk) * HW];
            mask = 1.f / (1.f + __expf(-mz));
        } else {
            mask = emB[(size_t)(g * 9 + kk) * HW];
        }

        float py = (float)(h - 1 + kh) + dy;
        float px = (float)(w - 1 + kw) + dx;
        float fy = floorf(py), fx = floorf(px);
        float ly = py - fy, lx = px - fx;
        int y0 = (int)fy, x0 = (int)fx;
        int y1 = y0 + 1, x1 = x0 + 1;

        float w00 = (1.f - ly) * (1.f - lx);
        float w01 = (1.f - ly) * lx;
        float w10 = ly * (1.f - lx);
        float w11 = ly * lx;
        if (y0 < 0 || y0 >= Hh)     { w00 = 0.f; w01 = 0.f; }
        if (y1 < 0 || y1 >= Hh)     { w10 = 0.f; w11 = 0.f; }
        if (x0 < 0 || x0 >= Wwidth) { w00 = 0.f; w10 = 0.f; }
        if (x1 < 0 || x1 >= Wwidth) { w01 = 0.f; w11 = 0.f; }

        int cy0 = min(max(y0, 0), Hh - 1),     cy1 = min(max(y1, 0), Hh - 1);
        int cx0 = min(max(x0, 0), Wwidth - 1), cx1 = min(max(x1, 0), Wwidth - 1);
        int i00 = (cy0 * Wwidth + cx0) * 8, i01 = (cy0 * Wwidth + cx1) * 8;
        int i10 = (cy1 * Wwidth + cx0) * 8, i11 = (cy1 * Wwidth + cx1) * 8;

        float4 r00 = *(const float4*)(src + i00);
        float4 r01 = *(const float4*)(src + i01);
        float4 r10 = *(const float4*)(src + i10);
        float4 r11 = *(const float4*)(src + i11);
        const __half2* h00 = (const __half2*)&r00;
        const __half2* h01 = (const __half2*)&r01;
        const __half2* h10 = (const __half2*)&r10;
        const __half2* h11 = (const __half2*)&r11;

        float vv[8];
        #pragma unroll
        for (int j2 = 0; j2 < 4; j2++) {
            float2 f00 = __half22float2(h00[j2]);
            float2 f01 = __half22float2(h01[j2]);
            float2 f10 = __half22float2(h10[j2]);
            float2 f11 = __half22float2(h11[j2]);
            vv[2 * j2]     = (w00 * f00.x + w01 * f01.x + w10 * f10.x + w11 * f11.x) * mask;
            vv[2 * j2 + 1] = (w00 * f00.y + w01 * f01.y + w10 * f10.y + w11 * f11.y) * mask;
        }

        #pragma unroll
        for (int c = 0; c < 8; c++) {
            ull xs = pk(vv[c], vv[c]);
            #pragma unroll
            for (int j = 0; j < 4; j++) {
                ull wp = *(const ull*)&s_w[c][kk][2 * j];
                acc[j] = ffma2(xs, wp, acc[j]);
            }
        }
    }

    float* ob = out + (size_t)half * Bn * 64 * HW + (size_t)(b * 64 + g * 8) * HW + pix;
    #pragma unroll
    for (int j = 0; j < 4; j++) {
        float v0, v1;
        upk(acc[j], v0, v1);
        ob[(size_t)(2 * j) * HW]     = v0 + s_b[2 * j];
        ob[(size_t)(2 * j + 1) * HW] = v1 + s_b[2 * j + 1];
    }
}

// ---------------------------------------------------------------------------
extern "C" void kernel_launch(void* const* d_in, const int* in_sizes, int n_in,
                              void* d_out, int out_size)
{
    const float* x      = (const float*)d_in[0];
    const float* share  = (const float*)d_in[1];
    const float* offF   = (const float*)d_in[2];
    const float* w_om   = (const float*)d_in[3];
    const float* b_om   = (const float*)d_in[4];
    const float* w_em1  = (const float*)d_in[5];
    const float* b_em1  = (const float*)d_in[6];
    const float* w_em2  = (const float*)d_in[7];
    const float* b_em2  = (const float*)d_in[8];
    const float* w_dc   = (const float*)d_in[9];
    const float* b_dc   = (const float*)d_in[10];
    float* out = (float*)d_out;

    float *pom, *pem;
    __half *pxh, *psh;
    bf16 *pofh, *pofl, *ptsh, *ptsl, *pe1h, *pe1l;
    bf16 *pwomh, *pwoml, *pwe1h, *pwe1l, *pwe2h, *pwe2l;
    cudaGetSymbolAddress((void**)&pom,  g_om);
    cudaGetSymbolAddress((void**)&pem,  g_em);
    cudaGetSymbolAddress((void**)&pxh,  g_xh);
    cudaGetSymbolAddress((void**)&psh,  g_sh);
    cudaGetSymbolAddress((void**)&pofh, g_ofh);
    cudaGetSymbolAddress((void**)&pofl, g_ofl);
    cudaGetSymbolAddress((void**)&ptsh, g_tsh);
    cudaGetSymbolAddress((void**)&ptsl, g_tsl);
    cudaGetSymbolAddress((void**)&pe1h, g_e1h);
    cudaGetSymbolAddress((void**)&pe1l, g_e1l);
    cudaGetSymbolAddress((void**)&pwomh, g_womh);
    cudaGetSymbolAddress((void**)&pwoml, g_woml);
    cudaGetSymbolAddress((void**)&pwe1h, g_we1h);
    cudaGetSymbolAddress((void**)&pwe1l, g_we1l);
    cudaGetSymbolAddress((void**)&pwe2h, g_we2h);
    cudaGetSymbolAddress((void**)&pwe2l, g_we2l);

    cudaFuncSetAttribute(conv_wmma_kernel<4, 4, 0>,
                         cudaFuncAttributeMaxDynamicSharedMemorySize, SMEM_CONV);
    cudaFuncSetAttribute(conv_wmma_kernel<8, 4, 1>,
                         cudaFuncAttributeMaxDynamicSharedMemorySize, SMEM_CONV);
    cudaFuncSetAttribute(conv_wmma_kernel<4, 4, 2>,
                         cudaFuncAttributeMaxDynamicSharedMemorySize, SMEM_CONV);

    // weight packing (tiny)
    pack_w_kernel<<<(256 * 576 + 255) / 256, 256>>>(w_om,  pwomh, pwoml, 216, 256, 64);
    pack_w_kernel<<<(64 * 1152 + 255) / 256, 256>>>(w_em1, pwe1h, pwe1l, 64, 64, 128);
    pack_w_kernel<<<(128 * 576 + 255) / 256, 256>>>(w_em2, pwe2h, pwe2l, 72, 128, 64);

    // input split+transpose to channel-interleaved bf16 hi/lo
    split_t_kernel<<<dim3(128, 4, 4), 128>>>(offF,  pofh, pofl);
    split_t_kernel<<<dim3(128, 4, 4), 128>>>(share, ptsh, ptsl);

    // convs on tensor cores
    conv_wmma_kernel<4, 4, 0><<<dim3(128, 4, 4), 256, SMEM_CONV>>>(
        pofh, pofl, pofh, pofl, pwomh, pwoml, b_om, pom, nullptr, nullptr, 216);
    conv_wmma_kernel<8, 4, 1><<<dim3(128, 4, 1), 256, SMEM_CONV>>>(
        ptsh, ptsl, pofh, pofl, pwe1h, pwe1l, b_em1, nullptr, pe1h, pe1l, 64);
    conv_wmma_kernel<4, 4, 2><<<dim3(128, 4, 2), 256, SMEM_CONV>>>(
        pe1h, pe1l, pe1h, pe1l, pwe2h, pwe2l, b_em2, pem, nullptr, nullptr, 72);

    // fp16 sampling layout for deform
    transpose_kernel<<<4096, 128>>>(x, pxh);
    transpose_kernel<<<4096, 128>>>(share, psh);

    // both deformable convolutions
    deform_kernel<<<dim3(128, 32), 256>>>(w_dc, b_dc, out);

    (void)in_sizes; (void)n_in; (void)out_size;
}

// round 4
// speedup vs baseline: 3.6988x; 1.6527x over previous
#include <cuda_runtime.h>
#include <cuda_fp16.h>
#include <mma.h>

using namespace nvcuda;
typedef unsigned long long ull;

#define Bn 4
#define Hh 128
#define Wwidth 128
#define HW (128*128)

// ---------------- packed fp32x2 helpers (deform kernel) ---------------------
__device__ __forceinline__ ull pk(float lo, float hi) {
    ull r; asm("mov.b64 %0, {%1,%2};" : "=l"(r) : "f"(lo), "f"(hi)); return r;
}
__device__ __forceinline__ void upk(ull v, float& lo, float& hi) {
    asm("mov.b64 {%0,%1}, %2;" : "=f"(lo), "=f"(hi) : "l"(v));
}
__device__ __forceinline__ ull ffma2(ull a, ull b, ull c) {
    ull d; asm("fma.rn.f32x2 %0, %1, %2, %3;" : "=l"(d) : "l"(a), "l"(b), "l"(c)); return d;
}

// -------- scratch --------
__device__ float  g_om [Bn*216*HW];            // conv_om raw (fp32 NCHW)
__device__ float  g_em [Bn*72*HW];             // sigmoid(conv em2) fp32 NCHW
// channel-interleaved fp16 planes: [b][chunk16][h][w][ci16]
__device__ __half g_xi [(size_t)Bn*64*HW];     // x      (deform sampling only)
__device__ __half g_si [(size_t)Bn*64*HW];     // share  (conv input + deform sampling)
__device__ __half g_ofi[(size_t)Bn*64*HW];     // offset_feat (conv input)
__device__ __half g_e1i[(size_t)Bn*64*HW];     // em1 output (conv input)
// packed fp16 weights [CoP][Ktot], K index = (chunk*9+tap)*16+ci
__device__ __half g_wom[256*576];
__device__ __half g_we1[64*1152];
__device__ __half g_we2[128*576];

// ---------------------------------------------------------------------------
// weight pack: w[Co][CIN][9] fp32 -> fp16 [CoP][CIN*9] with K reorder
// ---------------------------------------------------------------------------
__global__ void pack_w_kernel(const float* __restrict__ w, __half* __restrict__ d,
                              int Co, int CoP, int CIN)
{
    int idx = blockIdx.x * 256 + threadIdx.x;
    int Ktot = CIN * 9;
    if (idx >= CoP * Ktot) return;
    int co = idx / Ktot, k = idx % Ktot;
    int chunk = k / 144, rem = k % 144, tap = rem / 16, ci = rem % 16;
    int cin = chunk * 16 + ci;
    float v = (co < Co) ? w[((size_t)co * CIN + cin) * 9 + tap] : 0.f;
    d[idx] = __float2half_rn(v);
}

// ---------------------------------------------------------------------------
// input transpose: NCHW fp32 -> [b][chunk][h][w][ci16] fp16
// ---------------------------------------------------------------------------
__global__ void __launch_bounds__(128) split_t_kernel(
    const float* __restrict__ in, __half* __restrict__ o)
{
    const int px = threadIdx.x;
    const int h = blockIdx.x, chunk = blockIdx.y, b = blockIdx.z;
    const float* src = in + (size_t)(b * 64 + chunk * 16) * HW + h * Wwidth + px;
    __half hv[16];
    #pragma unroll
    for (int ci = 0; ci < 16; ci++) hv[ci] = __float2half_rn(src[(size_t)ci * HW]);
    size_t off = (((size_t)(b * 4 + chunk) * Hh + h) * Wwidth + px) * 16;
    ((uint4*)(o + off))[0] = ((const uint4*)hv)[0];
    ((uint4*)(o + off))[1] = ((const uint4*)hv)[1];
}

// ---------------------------------------------------------------------------
// Tensor-core implicit-GEMM 3x3 conv, pad=1, single-pass fp16 (fp32 accum).
// Block = one output row (128 px) x 64 co. 8 warps = 2 (coSub) x 4 (nSub).
// B fragments from channel-interleaved smem [3][132][16] (32B-aligned windows).
// ACT: 0 -> fp32 NCHW, 1 -> leaky + fp16 interleaved, 2 -> sigmoid fp32 NCHW.
// ---------------------------------------------------------------------------
#define XSZ (3*132*16)      // halves (input tile)
#define WSZ (64*144)        // halves (weights)
#define SMEM_CONV (64*136*4)   // epilogue fp32 plane dominates: 34816 B

template<int CHUNKS, int C0CHUNKS, int ACT>
__global__ void __launch_bounds__(256) conv_wmma_kernel(
    const __half* __restrict__ x0, const __half* __restrict__ x1,
    const __half* __restrict__ wA, const float* __restrict__ bias,
    float* __restrict__ outF, __half* __restrict__ outH, int Co)
{
    extern __shared__ __align__(16) char smem_raw[];
    __half* s_x = (__half*)smem_raw;                       // [3][132][16]
    __half* s_w = (__half*)(smem_raw + XSZ * 2);           // [64][144]
    float*  sEp = (float*)smem_raw;                        // [64][136] (aliased)

    const int tid = threadIdx.x;
    const int h = blockIdx.x, b = blockIdx.y, coTile = blockIdx.z;
    const int warp = tid >> 5;
    const int coSub = warp >> 2;       // 0..1
    const int nSub  = warp & 3;        // 0..3
    const int Ktot  = CHUNKS * 144;

    wmma::fragment<wmma::accumulator, 16, 16, 16, float> acc[2][2];
    #pragma unroll
    for (int cf = 0; cf < 2; cf++)
        #pragma unroll
        for (int nf = 0; nf < 2; nf++) wmma::fill_fragment(acc[cf][nf], 0.f);

    // zero halo columns (scol 0, 129..131): 3 rows x 4 cols x 16 half = 24 uint4
    if (tid < 24) {
        int r = tid / 8, q = tid % 8;
        const int cols[4] = {0, 129, 130, 131};
        int scol = cols[q >> 1];
        uint4 z = {0, 0, 0, 0};
        ((uint4*)(s_x + (r * 132 + scol) * 16))[q & 1] = z;
    }

    for (int chunk = 0; chunk < CHUNKS; chunk++) {
        // ---- input tile fill: 3 rows x 256 uint4
        const __half* base;
        if (chunk < C0CHUNKS)
            base = x0 + ((size_t)b * C0CHUNKS + chunk) * HW * 16;
        else
            base = x1 + ((size_t)b * (CHUNKS - C0CHUNKS) + (chunk - C0CHUNKS)) * HW * 16;
        for (int u = tid; u < 768; u += 256) {
            int r = u >> 8, c = u & 255;
            int row = h - 1 + r;
            uint4 v = {0, 0, 0, 0};
            if (row >= 0 && row < Hh)
                v = *(const uint4*)(base + (size_t)row * 2048 + c * 8);
            *(uint4*)(s_x + (r * 132 + 1) * 16 + c * 8) = v;
        }
        // ---- weights fill: 64 co x 18 uint4
        for (int u = tid; u < 1152; u += 256) {
            int co = u / 18, c = u - co * 18;
            *(uint4*)(s_w + co * 144 + c * 8) =
                *(const uint4*)(wA + (size_t)(coTile * 64 + co) * Ktot + chunk * 144 + c * 8);
        }
        __syncthreads();

        #pragma unroll
        for (int tap = 0; tap < 9; tap++) {
            const int dr = tap / 3, dc = tap % 3;
            wmma::fragment<wmma::matrix_a, 16, 16, 16, __half, wmma::row_major> af[2];
            #pragma unroll
            for (int cf = 0; cf < 2; cf++)
                wmma::load_matrix_sync(af[cf], s_w + (coSub * 32 + cf * 16) * 144 + tap * 16, 144);
            wmma::fragment<wmma::matrix_b, 16, 16, 16, __half, wmma::col_major> bfr[2];
            #pragma unroll
            for (int nf = 0; nf < 2; nf++) {
                int scol = nSub * 32 + nf * 16 + dc;
                wmma::load_matrix_sync(bfr[nf], s_x + (dr * 132 + scol) * 16, 16);
            }
            #pragma unroll
            for (int cf = 0; cf < 2; cf++)
                #pragma unroll
                for (int nf = 0; nf < 2; nf++)
                    wmma::mma_sync(acc[cf][nf], af[cf], bfr[nf], acc[cf][nf]);
        }
        __syncthreads();
    }

    // ---- epilogue: frags -> smem -> GMEM
    #pragma unroll
    for (int cf = 0; cf < 2; cf++)
        #pragma unroll
        for (int nf = 0; nf < 2; nf++)
            wmma::store_matrix_sync(sEp + (coSub * 32 + cf * 16) * 136 + (nSub * 32 + nf * 16),
                                    acc[cf][nf], 136, wmma::mem_row_major);
    __syncthreads();

    const int px = tid & 127;
    if (ACT == 1) {
        const int hs = tid >> 7;
        #pragma unroll
        for (int q = 0; q < 2; q++) {
            int ch = hs * 2 + q;
            __half hv[16];
            #pragma unroll
            for (int ci = 0; ci < 16; ci++) {
                int co = ch * 16 + ci;
                float v = sEp[co * 136 + px] + bias[co];
                v = (v >= 0.f) ? v : 0.1f * v;
                hv[ci] = __float2half_rn(v);
            }
            size_t o = (((size_t)(b * 4 + ch) * Hh + h) * Wwidth + px) * 16;
            ((uint4*)(outH + o))[0] = ((const uint4*)hv)[0];
            ((uint4*)(outH + o))[1] = ((const uint4*)hv)[1];
        }
    } else {
        for (int co = tid >> 7; co < 64; co += 2) {
            int oc = coTile * 64 + co;
            if (oc < Co) {
                float v = sEp[co * 136 + px] + bias[oc];
                if (ACT == 2) v = 1.f / (1.f + __expf(-v));
                outF[((size_t)b * Co + oc) * HW + h * Wwidth + px] = v;
            }
        }
    }
}

// ---------------------------------------------------------------------------
// Both deformable convs: warps 0-3 -> x_deform, warps 4-7 -> share_deform.
// Samples directly from the channel-interleaved fp16 planes.
// ---------------------------------------------------------------------------
__global__ void __launch_bounds__(256) deform_kernel(
    const float* __restrict__ w_dc, const float* __restrict__ b_dc,
    float* __restrict__ out)
{
    __shared__ __align__(16) float s_w[8][9][8];
    __shared__ float s_b[8];

    const int tid  = threadIdx.x;
    const int half = tid >> 7;
    const int w    = tid & 127;
    const int h    = blockIdx.x;
    const int bg   = blockIdx.y;
    const int b    = bg >> 3, g = bg & 7;

    for (int e = tid; e < 576; e += 256) {
        int c = e / 72, r = e % 72;
        int kk = r / 8, co = r % 8;
        s_w[c][kk][co] = w_dc[((size_t)(g * 8 + co) * 8 + c) * 9 + kk];
    }
    if (tid < 8) s_b[tid] = b_dc[g * 8 + tid];
    __syncthreads();

    const int pix = h * Wwidth + w;
    const float* omB = g_om + (size_t)b * 216 * HW + pix;
    const float* emB = g_em + (size_t)b * 72 * HW + pix;
    // interleaved plane: [b][chunk16][h][w][16]; this group's 8ch at +(g&1)*8
    const __half* src = (half ? g_si : g_xi)
                        + ((size_t)(b * 4 + (g >> 1)) * HW) * 16 + (g & 1) * 8;

    ull acc[4];
    #pragma unroll
    for (int j = 0; j < 4; j++) acc[j] = 0ull;

    #pragma unroll
    for (int kk = 0; kk < 9; kk++) {
        const int kh = kk / 3, kw = kk % 3;
        float dy = omB[(size_t)(g * 18 + 2 * kk) * HW];
        float dx = omB[(size_t)(g * 18 + 2 * kk + 1) * HW];
        float mask;
        if (half == 0) {
            float mz = omB[(size_t)(144 + g * 9 + kk) * HW];
            mask = 1.f / (1.f + __expf(-mz));
        } else {
            mask = emB[(size_t)(g * 9 + kk) * HW];
        }

        float py = (float)(h - 1 + kh) + dy;
        float px = (float)(w - 1 + kw) + dx;
        float fy = floorf(py), fx = floorf(px);
        float ly = py - fy, lx = px - fx;
        int y0 = (int)fy, x0 = (int)fx;
        int y1 = y0 + 1, x1 = x0 + 1;

        float w00 = (1.f - ly) * (1.f - lx);
        float w01 = (1.f - ly) * lx;
        float w10 = ly * (1.f - lx);
        float w11 = ly * lx;
        if (y0 < 0 || y0 >= Hh)     { w00 = 0.f; w01 = 0.f; }
        if (y1 < 0 || y1 >= Hh)     { w10 = 0.f; w11 = 0.f; }
        if (x0 < 0 || x0 >= Wwidth) { w00 = 0.f; w10 = 0.f; }
        if (x1 < 0 || x1 >= Wwidth) { w01 = 0.f; w11 = 0.f; }

        int cy0 = min(max(y0, 0), Hh - 1),     cy1 = min(max(y1, 0), Hh - 1);
        int cx0 = min(max(x0, 0), Wwidth - 1), cx1 = min(max(x1, 0), Wwidth - 1);
        int i00 = (cy0 * Wwidth + cx0) * 16, i01 = (cy0 * Wwidth + cx1) * 16;
        int i10 = (cy1 * Wwidth + cx0) * 16, i11 = (cy1 * Wwidth + cx1) * 16;

        float4 r00 = *(const float4*)(src + i00);
        float4 r01 = *(const float4*)(src + i01);
        float4 r10 = *(const float4*)(src + i10);
        float4 r11 = *(const float4*)(src + i11);
        const __half2* h00 = (const __half2*)&r00;
        const __half2* h01 = (const __half2*)&r01;
        const __half2* h10 = (const __half2*)&r10;
        const __half2* h11 = (const __half2*)&r11;

        float vv[8];
        #pragma unroll
        for (int j2 = 0; j2 < 4; j2++) {
            float2 f00 = __half22float2(h00[j2]);
            float2 f01 = __half22float2(h01[j2]);
            float2 f10 = __half22float2(h10[j2]);
            float2 f11 = __half22float2(h11[j2]);
            vv[2 * j2]     = (w00 * f00.x + w01 * f01.x + w10 * f10.x + w11 * f11.x) * mask;
            vv[2 * j2 + 1] = (w00 * f00.y + w01 * f01.y + w10 * f10.y + w11 * f11.y) * mask;
        }

        #pragma unroll
        for (int c = 0; c < 8; c++) {
            ull xs = pk(vv[c], vv[c]);
            #pragma unroll
            for (int j = 0; j < 4; j++) {
                ull wp = *(const ull*)&s_w[c][kk][2 * j];
                acc[j] = ffma2(xs, wp, acc[j]);
            }
        }
    }

    float* ob = out + (size_t)half * Bn * 64 * HW + (size_t)(b * 64 + g * 8) * HW + pix;
    #pragma unroll
    for (int j = 0; j < 4; j++) {
        float v0, v1;
        upk(acc[j], v0, v1);
        ob[(size_t)(2 * j) * HW]     = v0 + s_b[2 * j];
        ob[(size_t)(2 * j + 1) * HW] = v1 + s_b[2 * j + 1];
    }
}

// ---------------------------------------------------------------------------
extern "C" void kernel_launch(void* const* d_in, const int* in_sizes, int n_in,
                              void* d_out, int out_size)
{
    const float* x      = (const float*)d_in[0];
    const float* share  = (const float*)d_in[1];
    const float* offF   = (const float*)d_in[2];
    const float* w_om   = (const float*)d_in[3];
    const float* b_om   = (const float*)d_in[4];
    const float* w_em1  = (const float*)d_in[5];
    const float* b_em1  = (const float*)d_in[6];
    const float* w_em2  = (const float*)d_in[7];
    const float* b_em2  = (const float*)d_in[8];
    const float* w_dc   = (const float*)d_in[9];
    const float* b_dc   = (const float*)d_in[10];
    float* out = (float*)d_out;

    float *pom, *pem;
    __half *pxi, *psi, *pofi, *pe1i, *pwom, *pwe1, *pwe2;
    cudaGetSymbolAddress((void**)&pom,  g_om);
    cudaGetSymbolAddress((void**)&pem,  g_em);
    cudaGetSymbolAddress((void**)&pxi,  g_xi);
    cudaGetSymbolAddress((void**)&psi,  g_si);
    cudaGetSymbolAddress((void**)&pofi, g_ofi);
    cudaGetSymbolAddress((void**)&pe1i, g_e1i);
    cudaGetSymbolAddress((void**)&pwom, g_wom);
    cudaGetSymbolAddress((void**)&pwe1, g_we1);
    cudaGetSymbolAddress((void**)&pwe2, g_we2);

    // launches ordered so ncu (-s 5 -c 1) profiles conv_om (launch #6)
    pack_w_kernel<<<(256 * 576 + 255) / 256, 256>>>(w_om, pwom, 216, 256, 64);   // 1
    split_t_kernel<<<dim3(128, 4, 4), 128>>>(offF, pofi);                         // 2
    pack_w_kernel<<<(64 * 1152 + 255) / 256, 256>>>(w_em1, pwe1, 64, 64, 128);   // 3
    split_t_kernel<<<dim3(128, 4, 4), 128>>>(share, psi);                         // 4
    split_t_kernel<<<dim3(128, 4, 4), 128>>>(x, pxi);                             // 5
    conv_wmma_kernel<4, 4, 0><<<dim3(128, 4, 4), 256, SMEM_CONV>>>(               // 6
        pofi, pofi, pwom, b_om, pom, nullptr, 216);
    pack_w_kernel<<<(128 * 576 + 255) / 256, 256>>>(w_em2, pwe2, 72, 128, 64);   // 7
    conv_wmma_kernel<8, 4, 1><<<dim3(128, 4, 1), 256, SMEM_CONV>>>(               // 8
        psi, pofi, pwe1, b_em1, nullptr, pe1i, 64);
    conv_wmma_kernel<4, 4, 2><<<dim3(128, 4, 2), 256, SMEM_CONV>>>(               // 9
        pe1i, pe1i, pwe2, b_em2, pem, nullptr, 72);
    deform_kernel<<<dim3(128, 32), 256>>>(w_dc, b_dc, out);                       // 10

    (void)in_sizes; (void)n_in; (void)out_size;
}